// round 17
// baseline (speedup 1.0000x reference)
#include <cuda_runtime.h>
#include <cstdint>
#include <cmath>

#define TOKENS   16384
#define DMODEL   4096
#define NEXP     64
#define TOPK     8

#define TILE_T   128
#define KCH      32
#define NITER    (DMODEL / KCH)   // 128
#define THREADS  256

// smem: tf32 limb pairs {hi,lo} per element, row stride padded to 34 pairs
#define PSTRIDE  34
#define XPAIRS   (TILE_T * PSTRIDE)            // 4352
#define WPAIRS   (NEXP * PSTRIDE)              // 2176
#define XBYTES   (XPAIRS * 8)                  // 34816
#define STAGE_BYTES ((XPAIRS + WPAIRS) * 8)    // 52224
#define SMEM_TOTAL  (2 * STAGE_BYTES)          // 104448

#define T_F (-87.33654022f)
#define FLT_MIN_NORM 1.1754943508222875e-38
#define WIN_CLAMP 0.004f
#define WIN_GAP   0.003f
#define FIX_BLOCKS 256

__device__ int g_count;
__device__ int g_list[TOKENS];

__device__ __forceinline__ uint32_t smem_to_u32(const void* p) {
    uint32_t a;
    asm("{ .reg .u64 t; cvta.to.shared.u64 t, %1; cvt.u32.u64 %0, t; }" : "=r"(a) : "l"(p));
    return a;
}
__device__ __forceinline__ uint32_t tf32_rna(float v) {
    uint32_t r;
    asm("cvt.rna.tf32.f32 %0, %1;" : "=r"(r) : "f"(v));
    return r;
}
// split float4 into tf32 {hi,lo} pairs and store 2x16B
__device__ __forceinline__ void split_sts(float4 v, uint32_t addr) {
    uint32_t h0 = tf32_rna(v.x), h1 = tf32_rna(v.y), h2 = tf32_rna(v.z), h3 = tf32_rna(v.w);
    uint32_t l0 = tf32_rna(v.x - __uint_as_float(h0));
    uint32_t l1 = tf32_rna(v.y - __uint_as_float(h1));
    uint32_t l2 = tf32_rna(v.z - __uint_as_float(h2));
    uint32_t l3 = tf32_rna(v.w - __uint_as_float(h3));
    asm volatile("st.shared.v4.b32 [%0], {%1,%2,%3,%4};" :: "r"(addr),      "r"(h0), "r"(l0), "r"(h1), "r"(l1) : "memory");
    asm volatile("st.shared.v4.b32 [%0], {%1,%2,%3,%4};" :: "r"(addr + 16), "r"(h2), "r"(l2), "r"(h3), "r"(l3) : "memory");
}
#define LDS64(h, l, addr) \
    asm volatile("ld.shared.v2.b32 {%0,%1}, [%2];" : "=r"(h), "=r"(l) : "r"(addr))

__device__ __forceinline__ void mma_tf32(float* d,
                                         uint32_t a0, uint32_t a1, uint32_t a2, uint32_t a3,
                                         uint32_t b0, uint32_t b1) {
    asm volatile(
        "mma.sync.aligned.m16n8k8.row.col.f32.tf32.tf32.f32 "
        "{%0,%1,%2,%3}, {%4,%5,%6,%7}, {%8,%9}, {%0,%1,%2,%3};"
        : "+f"(d[0]), "+f"(d[1]), "+f"(d[2]), "+f"(d[3])
        : "r"(a0), "r"(a1), "r"(a2), "r"(a3), "r"(b0), "r"(b1));
}

__global__ void reset_kernel() { if (threadIdx.x == 0) g_count = 0; }

// ---------------- kernel 1: 3xTF32 mma.sync GEMM + epilogue + flagging ----------------
__global__ void __launch_bounds__(THREADS, 1)
router_kernel(const float* __restrict__ x, const float* __restrict__ w,
              float* __restrict__ out_w, float* __restrict__ out_i)
{
    extern __shared__ char smem[];
    const uint32_t smem_u = smem_to_u32(smem);
    const int tid  = threadIdx.x;
    const int lane = tid & 31;
    const int w8   = tid >> 5;         // warp 0..7: token rows [16*w8, 16*w8+16)
    const int r    = lane >> 2;        // 0..7
    const int c    = lane & 3;         // 0..3
    const int t_block = blockIdx.x * TILE_T;

    float acc[8][4];
#pragma unroll
    for (int nt = 0; nt < 8; nt++)
#pragma unroll
        for (int q = 0; q < 4; q++) acc[nt][q] = 0.0f;

    // loader mapping: x = 1024 float4/stage (4/thread), w = 512 float4 (2/thread)
    const float* xsrc[4]; uint32_t xdst[4];
#pragma unroll
    for (int u = 0; u < 4; u++) {
        int seg = tid + THREADS * u;
        int row = seg >> 3, k = (seg & 7) * 4;
        xsrc[u] = x + (size_t)(t_block + row) * DMODEL + k;
        xdst[u] = (uint32_t)(row * PSTRIDE + k) * 8;
    }
    const float* wsrc[2]; uint32_t wdst[2];
#pragma unroll
    for (int u = 0; u < 2; u++) {
        int seg = tid + THREADS * u;
        int row = seg >> 3, k = (seg & 7) * 4;
        wsrc[u] = w + (size_t)row * DMODEL + k;
        wdst[u] = (uint32_t)(row * PSTRIDE + k) * 8;
    }

    float4 cx[4], cw_[2];
#pragma unroll
    for (int u = 0; u < 4; u++) cx[u] = *(const float4*)(xsrc[u]);
#pragma unroll
    for (int u = 0; u < 2; u++) cw_[u] = *(const float4*)(wsrc[u]);

    for (int it = 0; it < NITER; it++) {
        uint32_t xs = smem_u + (uint32_t)(it & 1) * STAGE_BYTES;
        uint32_t ws = xs + XBYTES;

#pragma unroll
        for (int u = 0; u < 4; u++) split_sts(cx[u], xs + xdst[u]);
#pragma unroll
        for (int u = 0; u < 2; u++) split_sts(cw_[u], ws + wdst[u]);
        __syncthreads();

        if (it + 1 < NITER) {
            int kc = (it + 1) * KCH;
#pragma unroll
            for (int u = 0; u < 4; u++) cx[u] = *(const float4*)(xsrc[u] + kc);
#pragma unroll
            for (int u = 0; u < 2; u++) cw_[u] = *(const float4*)(wsrc[u] + kc);
        }

        // compute: 4 x k8-steps, per step 8 n-tiles x 3 limb products
#pragma unroll
        for (int k8 = 0; k8 < 4; k8++) {
            int k0 = k8 * 8;
            uint32_t ah0, al0, ah1, al1, ah2, al2, ah3, al3;
            uint32_t abase = xs + (uint32_t)(((16 * w8 + r) * PSTRIDE) + k0 + c) * 8;
            LDS64(ah0, al0, abase);                              // a0: (r,   c)
            LDS64(ah1, al1, abase + 8u * PSTRIDE * 8u);          // a1: (r+8, c)
            LDS64(ah2, al2, abase + 32u);                        // a2: (r,   c+4)
            LDS64(ah3, al3, abase + 8u * PSTRIDE * 8u + 32u);    // a3: (r+8, c+4)
#pragma unroll
            for (int nt = 0; nt < 8; nt++) {
                uint32_t bbase = ws + (uint32_t)(((nt * 8 + r) * PSTRIDE) + k0 + c) * 8;
                uint32_t bh0, bl0, bh1, bl1;
                LDS64(bh0, bl0, bbase);          // b0: (k=c,   n=r)
                LDS64(bh1, bl1, bbase + 32u);    // b1: (k=c+4, n=r)
                mma_tf32(acc[nt], ah0, ah1, ah2, ah3, bh0, bh1);   // hi*hi
                mma_tf32(acc[nt], al0, al1, al2, al3, bh0, bh1);   // lo*hi
                mma_tf32(acc[nt], ah0, ah1, ah2, ah3, bl0, bl1);   // hi*lo
            }
        }
    }
    __syncthreads();

    // write logits to lsm [128][65] (reuses stage smem)
    float* lsm = (float*)smem;
    {
        int row0 = 16 * w8 + r;
#pragma unroll
        for (int nt = 0; nt < 8; nt++) {
            int col = nt * 8 + 2 * c;
            lsm[row0 * 65 + col]           = acc[nt][0];
            lsm[row0 * 65 + col + 1]       = acc[nt][1];
            lsm[(row0 + 8) * 65 + col]     = acc[nt][2];
            lsm[(row0 + 8) * 65 + col + 1] = acc[nt][3];
        }
    }
    __syncthreads();

    if (tid < TILE_T) {
        const float* row = lsm + tid * 65;

        float m = row[0];
#pragma unroll 8
        for (int e = 1; e < NEXP; e++) m = fmaxf(m, row[e]);

        float sum = 0.0f;
        for (int e = 0; e < NEXP; e++) {
            float d = row[e] - m;
            if (d >= T_F) sum += __expf(d);
        }
        float rinv = 1.0f / sum;
        float bnd  = T_F + __logf(sum);

        // ---- ambiguity flags (R14 config, protected) ----
        float dt[9];
#pragma unroll
        for (int q = 0; q < 9; q++) dt[q] = -3.0e38f;
        bool flag = false;
        for (int e = 0; e < NEXP; e++) {
            float d = row[e] - m;
            if (fabsf(d - T_F) < WIN_CLAMP || fabsf(d - bnd) < WIN_CLAMP) flag = true;
            if (d > dt[8]) {
                dt[8] = d;
#pragma unroll
                for (int q = 8; q > 0; q--)
                    if (dt[q] > dt[q - 1]) { float t = dt[q]; dt[q] = dt[q - 1]; dt[q - 1] = t; }
            }
        }
#pragma unroll
        for (int q = 0; q < 8; q++)
            if (dt[q] - dt[q + 1] < WIN_GAP && dt[q + 1] > T_F - WIN_CLAMP) flag = true;

        int gtok = t_block + tid;
        if (flag) {
            int slot = atomicAdd(&g_count, 1);
            if (slot < TOKENS) g_list[slot] = gtok;
        }

        // ---- fast fp32 epilogue (flagged tokens overwritten by fp64 fixup) ----
        int keys[TOPK];
        int idxs[TOPK];
#pragma unroll
        for (int j = 0; j < TOPK; j++) { keys[j] = -1; idxs[j] = 0; }

        float qc = __expf(T_F) * rinv;
        const int key_clamp = (qc < FLT_MIN_NORM) ? 0 : __float_as_int(qc);

        for (int e = 0; e < NEXP; e++) {
            float d = row[e] - m;
            int key;
            if (d < T_F) key = key_clamp;
            else {
                float qf = __expf(d) * rinv;
                key = (qf < FLT_MIN_NORM) ? 0 : __float_as_int(qf);
            }
            if (key > keys[TOPK - 1]) {
                keys[TOPK - 1] = key;
                idxs[TOPK - 1] = e;
#pragma unroll
                for (int q2 = TOPK - 1; q2 > 0; q2--) {
                    if (keys[q2] > keys[q2 - 1]) {
                        int tk = keys[q2]; keys[q2] = keys[q2 - 1]; keys[q2 - 1] = tk;
                        int ti = idxs[q2]; idxs[q2] = idxs[q2 - 1]; idxs[q2 - 1] = ti;
                    }
                }
            }
        }

#pragma unroll
        for (int j = 0; j < TOPK; j++) {
            out_w[(size_t)gtok * TOPK + j] = __int_as_float(keys[j] < 0 ? 0 : keys[j]);
            out_i[(size_t)gtok * TOPK + j] = (float)idxs[j];
        }
    }
}

// ---------------- kernel 2: fp64 re-resolution, parallel epilogue (R14, protected) ----------------
__global__ void __launch_bounds__(256, 1)
router_fixup(const float* __restrict__ x, const float* __restrict__ w,
             float* __restrict__ out_w, float* __restrict__ out_i)
{
    __shared__ float  lg[NEXP];
    __shared__ int    skey[NEXP];
    __shared__ float  s_m;
    __shared__ double s_sumd;

    const int tid  = threadIdx.x;
    const int wid  = tid >> 5;
    const int lane = tid & 31;

    int total = g_count;
    if (total > TOKENS) total = TOKENS;

    for (int li = blockIdx.x; li < total; li += FIX_BLOCKS) {
        int tok = g_list[li];
        const float* xr = x + (size_t)tok * DMODEL;
        const float* w0 = w + (size_t)(wid * 8) * DMODEL;

        double acc[8];
#pragma unroll
        for (int e8 = 0; e8 < 8; e8++) acc[e8] = 0.0;

        for (int k = lane; k < DMODEL; k += 32) {
            double xv = (double)xr[k];
#pragma unroll
            for (int e8 = 0; e8 < 8; e8++)
                acc[e8] = fma(xv, (double)w0[e8 * DMODEL + k], acc[e8]);
        }

#pragma unroll
        for (int e8 = 0; e8 < 8; e8++) {
            double s = acc[e8];
#pragma unroll
            for (int o = 16; o; o >>= 1) s += __shfl_down_sync(0xFFFFFFFFu, s, o);
            if (lane == 0) lg[wid * 8 + e8] = (float)s;
        }
        __syncthreads();

        if (tid == 0) {
            float m = lg[0];
#pragma unroll 8
            for (int e = 1; e < NEXP; e++) m = fmaxf(m, lg[e]);
            float sum = 0.0f;
            for (int e = 0; e < NEXP; e++) {
                float d = lg[e] - m;
                if (d >= T_F) sum += __expf(d);
            }
            s_m = m;
            s_sumd = (double)sum;
        }
        __syncthreads();

        if (tid < NEXP) {
            float d = lg[tid] - s_m;
            double dd = (d < T_F) ? (double)T_F : (double)d;
            double q  = exp(dd) / s_sumd;
            skey[tid] = (q < FLT_MIN_NORM) ? 0 : __float_as_int((float)q);
        }
        __syncthreads();

        if (tid == 0) {
            int keys[TOPK];
            int idxs[TOPK];
#pragma unroll
            for (int j = 0; j < TOPK; j++) { keys[j] = -1; idxs[j] = 0; }

            for (int e = 0; e < NEXP; e++) {
                int key = skey[e];
                if (key > keys[TOPK - 1]) {
                    keys[TOPK - 1] = key;
                    idxs[TOPK - 1] = e;
#pragma unroll
                    for (int q2 = TOPK - 1; q2 > 0; q2--) {
                        if (keys[q2] > keys[q2 - 1]) {
                            int tk = keys[q2]; keys[q2] = keys[q2 - 1]; keys[q2 - 1] = tk;
                            int ti = idxs[q2]; idxs[q2] = idxs[q2 - 1]; idxs[q2 - 1] = ti;
                        }
                    }
                }
            }
#pragma unroll
            for (int j = 0; j < TOPK; j++) {
                out_w[(size_t)tok * TOPK + j] = __int_as_float(keys[j] < 0 ? 0 : keys[j]);
                out_i[(size_t)tok * TOPK + j] = (float)idxs[j];
            }
        }
        __syncthreads();
    }
}

extern "C" void kernel_launch(void* const* d_in, const int* in_sizes, int n_in,
                              void* d_out, int out_size)
{
    const float* x = (const float*)d_in[0];
    const float* w = (const float*)d_in[1];

    float* out_w = (float*)d_out;
    float* out_i = (float*)d_out + (size_t)TOKENS * TOPK;

    cudaFuncSetAttribute(router_kernel,
                         cudaFuncAttributeMaxDynamicSharedMemorySize, SMEM_TOTAL);

    reset_kernel<<<1, 32>>>();
    router_kernel<<<TOKENS / TILE_T, THREADS, SMEM_TOTAL>>>(x, w, out_w, out_i);
    router_fixup<<<FIX_BLOCKS, 256>>>(x, w, out_w, out_i);
}